// round 12
// baseline (speedup 1.0000x reference)
#include <cuda_runtime.h>
#include <math.h>

#define H 1024
#define V 50257
#define S 4096
#define NT 256

// ---------------- scratch (__device__ globals) ----------------
__device__ float g_gi[3 * H];
__device__ float g_gh[3 * H];
__device__ float g_h[H];
__device__ float g_vpart[16][H];     // 16 j-chunks of 64 rows
__device__ float g_scores[S];
__device__ float g_ctxpart[64][H];   // 64 s-chunks of 64 rows
__device__ float g_ctx[H];
__device__ unsigned g_cnt = 0;
__device__ unsigned g_gen = 0;

// ---------------- helpers ----------------
__device__ __forceinline__ float warp_sum(float v) {
#pragma unroll
    for (int o = 16; o; o >>= 1) v += __shfl_xor_sync(0xffffffffu, v, o);
    return v;
}

__device__ __forceinline__ void grid_sync() {
    __syncthreads();
    if (threadIdx.x == 0) {
        __threadfence();
        unsigned gen = *(volatile unsigned*)&g_gen;
        if (atomicAdd(&g_cnt, 1u) == gridDim.x - 1) {
            g_cnt = 0;
            __threadfence();
            *(volatile unsigned*)&g_gen = gen + 1;
        } else {
            while (*(volatile unsigned*)&g_gen == gen) __nanosleep(32);
        }
        __threadfence();
    }
    __syncthreads();
}

// ---------------- ONE kernel: chain + logits, register-capped for 48 warps/SM --
__global__ void __launch_bounds__(NT, 6)
k_all(const int* __restrict__ word,
      const float* __restrict__ last_hidden,
      const float* __restrict__ enc,
      const float* __restrict__ emb,
      const float* __restrict__ w_ih,
      const float* __restrict__ w_hh,
      const float* __restrict__ b_ih,
      const float* __restrict__ b_hh,
      const float* __restrict__ attn_w,
      const float* __restrict__ out_w,
      const float* __restrict__ out_b,
      float* __restrict__ dout) {
    __shared__ float4 sbuf4[512];   // P1: [x | h_prev] ; P2: [h | h_prev] ; P3+: [h | v] ; P6: [h | ctx]
    __shared__ float red[8];
    __shared__ float bcm, bcs;
    __shared__ float w_sh[64];

    const int t = threadIdx.x;
    const int b = blockIdx.x;
    const int warp = t >> 5, lane = t & 31;
    const int nwarp = gridDim.x * (NT / 32);
    const int gw = b * (NT / 32) + warp;

    // ===== P1: gates — one row per warp (nwarp >= 6144 with grid >= 768)
    {
        const float* x = emb + (long)word[0] * H;
        sbuf4[t]       = reinterpret_cast<const float4*>(x)[t];
        sbuf4[256 + t] = reinterpret_cast<const float4*>(last_hidden)[t];
        __syncthreads();
        if (gw < 6 * H) {
            const float4* p;
            const float4* vec;
            float bias;
            float* outp;
            if (gw < 3 * H) {
                p = reinterpret_cast<const float4*>(w_ih + (long)gw * H);
                vec = sbuf4; bias = b_ih[gw]; outp = &g_gi[gw];
            } else {
                int rr = gw - 3 * H;
                p = reinterpret_cast<const float4*>(w_hh + (long)rr * H);
                vec = sbuf4 + 256; bias = b_hh[rr]; outp = &g_gh[rr];
            }
            float acc = 0.f;
#pragma unroll
            for (int it = 0; it < 8; it++) {
                float4 w = p[it * 32 + lane];
                float4 c = vec[it * 32 + lane];
                acc += w.x * c.x + w.y * c.y + w.z * c.z + w.w * c.w;
            }
            acc = warp_sum(acc);
            if (!lane) *outp = acc + bias;
        }
    }
    grid_sync();   // B1

    // ===== P2 (blocks 0..63): local GRU -> smem h, then v partials
    if (b < 64) {
        float* h_sh = (float*)sbuf4;             // overwrites x (done)
#pragma unroll
        for (int k = 0; k < 4; k++) {
            int i = t + NT * k;
            float hp = ((const float*)(sbuf4 + 256))[i];   // h_prev still live
            float r = 1.f / (1.f + expf(-(g_gi[i] + g_gh[i])));
            float z = 1.f / (1.f + expf(-(g_gi[H + i] + g_gh[H + i])));
            float n = tanhf(g_gi[2 * H + i] + r * g_gh[2 * H + i]);
            float h = (1.f - z) * n + z * hp;
            h_sh[i] = h;
            if (b == 0) { g_h[i] = h; dout[V + i] = h; }   // hidden output + publish
        }
        __syncthreads();

        int jc = b >> 2;                          // 16 chunks of 64 rows
        int c = (b & 3) * NT + t;
        const float* base = attn_w + (long)(jc * 64) * H + c;
        float s = 0.f;
#pragma unroll 8
        for (int j = 0; j < 64; j++)
            s += base[(long)j * H] * h_sh[jc * 64 + j];
        g_vpart[jc][c] = s;
    }
    grid_sync();   // B2

    // ===== P3: local vred (all blocks) -> smem v ; scores one row per warp
    {
        float4 acc = make_float4(0.f, 0.f, 0.f, 0.f);
#pragma unroll
        for (int j = 0; j < 16; j++) {
            float4 pv = reinterpret_cast<const float4*>(g_vpart[j])[t];
            acc.x += pv.x; acc.y += pv.y; acc.z += pv.z; acc.w += pv.w;
        }
        sbuf4[256 + t] = acc;                     // v replaces h_prev
        __syncthreads();
        if (gw < S) {
            const float4* er = reinterpret_cast<const float4*>(enc + (long)gw * H);
            float a = 0.f;
#pragma unroll
            for (int it = 0; it < 8; it++) {
                float4 e = er[it * 32 + lane];
                float4 vv = sbuf4[256 + it * 32 + lane];
                a += e.x * vv.x + e.y * vv.y + e.z * vv.z + e.w * vv.w;
            }
            a = warp_sum(a);
            if (!lane) g_scores[gw] = a;          // attn_b softmax-invariant, dropped
        }
    }
    grid_sync();   // B3

    // ===== P4 (blocks 0..255): two-pass softmax stats + ctx partials
    if (b < 256) {
        // pass 1: max
        float m = -INFINITY;
#pragma unroll
        for (int k = 0; k < 16; k++) m = fmaxf(m, g_scores[t + NT * k]);
#pragma unroll
        for (int o = 16; o; o >>= 1) m = fmaxf(m, __shfl_xor_sync(0xffffffffu, m, o));
        if (!lane) red[warp] = m;
        __syncthreads();
        if (warp == 0) {
            m = (lane < 8) ? red[lane] : -INFINITY;
#pragma unroll
            for (int o = 4; o; o >>= 1) m = fmaxf(m, __shfl_xor_sync(0xffffffffu, m, o));
            if (!lane) bcm = m;
        }
        __syncthreads();
        m = bcm;
        // pass 2: sum of exp (re-read scores; L2-hot)
        float sum = 0.f;
#pragma unroll
        for (int k = 0; k < 16; k++) sum += expf(g_scores[t + NT * k] - m);
        sum = warp_sum(sum);
        __syncthreads();
        if (!lane) red[warp] = sum;
        __syncthreads();
        if (warp == 0) {
            sum = (lane < 8) ? red[lane] : 0.f;
#pragma unroll
            for (int o = 4; o; o >>= 1) sum += __shfl_xor_sync(0xffffffffu, sum, o);
            if (!lane) bcs = sum;
        }
        __syncthreads();
        const float inv = 1.f / bcs;

        if (b == 0) {                             // attn_weights output
#pragma unroll
            for (int k = 0; k < 16; k++) {
                int s = t + NT * k;
                dout[V + H + s] = expf(g_scores[s] - m) * inv;
            }
        }

        const int sc = b >> 2;                    // rows [sc*64, sc*64+64)
        const int c = (b & 3) * NT + t;
        if (t < 64) w_sh[t] = expf(g_scores[sc * 64 + t] - m) * inv;
        __syncthreads();

        const float* base = enc + (long)(sc * 64) * H + c;
        float acc = 0.f;
#pragma unroll 8
        for (int s = 0; s < 64; s++)
            acc += w_sh[s] * base[(long)s * H];
        g_ctxpart[sc][c] = acc;
    }
    grid_sync();   // B4

    // ===== P5 (blocks 0..3): ctx reduce
    if (b < 4) {
        int c = b * NT + t;
        float s = 0.f;
#pragma unroll
        for (int j = 0; j < 64; j++) s += g_ctxpart[j][c];
        g_ctx[c] = s;
    }
    grid_sync();   // B5

    // ===== P6: logits — grid-stride warp-per-row over the 412MB stream
    {
        sbuf4[t]       = reinterpret_cast<const float4*>(g_h)[t];
        sbuf4[256 + t] = reinterpret_cast<const float4*>(g_ctx)[t];
        __syncthreads();
        for (int r = gw; r < V; r += nwarp) {
            const float4* wr = reinterpret_cast<const float4*>(out_w + (long)r * (2 * H));
            float acc = 0.f;
#pragma unroll
            for (int it = 0; it < 16; it++) {
                float4 w = wr[it * 32 + lane];
                float4 c = sbuf4[it * 32 + lane];
                acc += w.x * c.x + w.y * c.y + w.z * c.z + w.w * c.w;
            }
            acc = warp_sum(acc);
            if (!lane) dout[r] = acc + out_b[r];
        }
    }
}

// ---------------- launch ----------------
extern "C" void kernel_launch(void* const* d_in, const int* in_sizes, int n_in,
                              void* d_out, int out_size) {
    const int* word = (const int*)d_in[0];
    const float* last_hidden = (const float*)d_in[1];
    const float* enc = (const float*)d_in[2];
    const float* emb = (const float*)d_in[3];
    const float* w_ih = (const float*)d_in[4];
    const float* w_hh = (const float*)d_in[5];
    const float* b_ih = (const float*)d_in[6];
    const float* b_hh = (const float*)d_in[7];
    const float* attn_w = (const float*)d_in[8];
    // d_in[9] = attn_b : constant pre-softmax shift -> softmax-invariant, dropped
    const float* out_w = (const float*)d_in[10];
    const float* out_b = (const float*)d_in[11];
    float* dout = (float*)d_out;

    // co-residency-guaranteed persistent grid (occupancy API is authoritative)
    static int nb = 0;
    if (!nb) {
        int dev = 0, sms = 0, per_sm = 0;
        cudaGetDevice(&dev);
        cudaDeviceGetAttribute(&sms, cudaDevAttrMultiProcessorCount, dev);
        cudaOccupancyMaxActiveBlocksPerMultiprocessor(&per_sm, k_all, NT, 0);
        nb = sms * per_sm;          // expect 152 * 6 = 912
    }

    k_all<<<nb, NT>>>(word, last_hidden, enc, emb, w_ih, w_hh, b_ih, b_hh,
                      attn_w, out_w, out_b, dout);
}

// round 13
// speedup vs baseline: 1.4044x; 1.4044x over previous
#include <cuda_runtime.h>
#include <math.h>

#define H 1024
#define V 50257
#define S 4096
#define NT 256
#define NMID 256        // persistent mid-chain blocks (co-resident at 2/SM)

// ---------------- scratch (__device__ globals) ----------------
__device__ float g_gi[3 * H];
__device__ float g_gh[3 * H];
__device__ float g_h[H];
__device__ float g_vpart[16][H];     // 16 j-chunks of 64 rows
__device__ float g_scores[S];
__device__ float g_ctxpart[64][H];   // 64 s-chunks of 64 rows
__device__ float g_ctx[H];
__device__ unsigned g_cnt = 0;
__device__ unsigned g_gen = 0;

// ---------------- helpers ----------------
__device__ __forceinline__ float warp_sum(float v) {
#pragma unroll
    for (int o = 16; o; o >>= 1) v += __shfl_xor_sync(0xffffffffu, v, o);
    return v;
}

__device__ __forceinline__ void mid_sync() {
    __syncthreads();
    if (threadIdx.x == 0) {
        __threadfence();
        unsigned gen = *(volatile unsigned*)&g_gen;
        if (atomicAdd(&g_cnt, 1u) == NMID - 1) {
            g_cnt = 0;
            __threadfence();
            *(volatile unsigned*)&g_gen = gen + 1;
        } else {
            while (*(volatile unsigned*)&g_gen == gen) { }
        }
        __threadfence();
    }
    __syncthreads();
}

// ================= K1: gates — FLAT, k_logits-shaped (768 blocks, retire) =====
// row r: r<3H -> g_gi[r] = w_ih[r].x + b_ih[r] ; else g_gh[r-3H] = w_hh.h_prev + b_hh
__global__ void k_gates(const int* __restrict__ word,
                        const float* __restrict__ last_hidden,
                        const float* __restrict__ emb,
                        const float* __restrict__ w_ih,
                        const float* __restrict__ w_hh,
                        const float* __restrict__ b_ih,
                        const float* __restrict__ b_hh) {
    __shared__ float4 xv[256];    // x = emb[word]
    __shared__ float4 hv[256];    // h_prev
    int t = threadIdx.x;
    const float* x = emb + (long)word[0] * H;
    xv[t] = reinterpret_cast<const float4*>(x)[t];
    hv[t] = reinterpret_cast<const float4*>(last_hidden)[t];
    __syncthreads();

    int warp = t >> 5, lane = t & 31;
    int r = blockIdx.x * 8 + warp;          // 768 blocks x 8 warps = 6144 rows
    const float4* p;
    const float4* vec;
    float bias;
    float* outp;
    if (r < 3 * H) {
        p = reinterpret_cast<const float4*>(w_ih + (long)r * H);
        vec = xv; bias = b_ih[r]; outp = &g_gi[r];
    } else {
        int rr = r - 3 * H;
        p = reinterpret_cast<const float4*>(w_hh + (long)rr * H);
        vec = hv; bias = b_hh[rr]; outp = &g_gh[rr];
    }
    float acc = 0.f;
#pragma unroll
    for (int it = 0; it < 8; it++) {
        float4 w = p[it * 32 + lane];
        float4 c = vec[it * 32 + lane];
        acc += w.x * c.x + w.y * c.y + w.z * c.z + w.w * c.w;
    }
    acc = warp_sum(acc);
    if (!lane) *outp = acc + bias;
}

// ================= K2: mid-chain (persistent 256 blocks, 3 barriers) ==========
__global__ void __launch_bounds__(NT, 2)
k_mid(const float* __restrict__ last_hidden,
      const float* __restrict__ enc,
      const float* __restrict__ attn_w,
      float* __restrict__ dout) {
    __shared__ float4 sbuf4[512];   // [0..255]: h ; [256..511]: v
    __shared__ float red[8];
    __shared__ float bcm, bcs;
    __shared__ float w_sh[64];
    float* h_sh = (float*)sbuf4;

    const int t = threadIdx.x;
    const int b = blockIdx.x;
    const int warp = t >> 5, lane = t & 31;

    // ===== P1 (blocks 0..63): local GRU -> smem h ; v partials
    if (b < 64) {
#pragma unroll
        for (int k = 0; k < 4; k++) {
            int i = t + NT * k;
            float hp = last_hidden[i];
            float r = 1.f / (1.f + expf(-(g_gi[i] + g_gh[i])));
            float z = 1.f / (1.f + expf(-(g_gi[H + i] + g_gh[H + i])));
            float n = tanhf(g_gi[2 * H + i] + r * g_gh[2 * H + i]);
            float h = (1.f - z) * n + z * hp;
            h_sh[i] = h;
            if (b == 0) { g_h[i] = h; dout[V + i] = h; }   // hidden output + publish
        }
        __syncthreads();

        int jc = b >> 2;                          // 16 chunks of 64 rows
        int c = (b & 3) * NT + t;
        const float* base = attn_w + (long)(jc * 64) * H + c;
        float s = 0.f;
#pragma unroll 8
        for (int j = 0; j < 64; j++)
            s += base[(long)j * H] * h_sh[jc * 64 + j];
        g_vpart[jc][c] = s;
    }
    mid_sync();   // B1

    // ===== P2: local vred (all) -> smem v ; scores 2 rows/warp interleaved
    {
        float4 acc = make_float4(0.f, 0.f, 0.f, 0.f);
#pragma unroll
        for (int j = 0; j < 16; j++) {
            float4 pv = reinterpret_cast<const float4*>(g_vpart[j])[t];
            acc.x += pv.x; acc.y += pv.y; acc.z += pv.z; acc.w += pv.w;
        }
        sbuf4[256 + t] = acc;
        __syncthreads();

        int gw = b * 8 + warp;                    // 2048 warps, rows gw, gw+2048
        const float4* e0 = reinterpret_cast<const float4*>(enc + (long)gw * H);
        const float4* e1 = reinterpret_cast<const float4*>(enc + (long)(gw + 2048) * H);
        float a0 = 0.f, a1 = 0.f;
#pragma unroll
        for (int it = 0; it < 8; it++) {
            float4 x0 = e0[it * 32 + lane];
            float4 x1 = e1[it * 32 + lane];
            float4 vv = sbuf4[256 + it * 32 + lane];
            a0 += x0.x * vv.x + x0.y * vv.y + x0.z * vv.z + x0.w * vv.w;
            a1 += x1.x * vv.x + x1.y * vv.y + x1.z * vv.z + x1.w * vv.w;
        }
        a0 = warp_sum(a0); a1 = warp_sum(a1);
        if (!lane) { g_scores[gw] = a0; g_scores[gw + 2048] = a1; }
        // attn_b is a constant pre-softmax shift -> softmax-invariant, dropped
    }
    mid_sync();   // B2

    // ===== P3: local two-pass softmax stats ; ctx partials (all 256 blocks)
    {
        float m = -INFINITY;
#pragma unroll
        for (int k = 0; k < 16; k++) m = fmaxf(m, g_scores[t + NT * k]);
#pragma unroll
        for (int o = 16; o; o >>= 1) m = fmaxf(m, __shfl_xor_sync(0xffffffffu, m, o));
        if (!lane) red[warp] = m;
        __syncthreads();
        if (warp == 0) {
            m = (lane < 8) ? red[lane] : -INFINITY;
#pragma unroll
            for (int o = 4; o; o >>= 1) m = fmaxf(m, __shfl_xor_sync(0xffffffffu, m, o));
            if (!lane) bcm = m;
        }
        __syncthreads();
        m = bcm;
        float sum = 0.f;
#pragma unroll
        for (int k = 0; k < 16; k++) sum += expf(g_scores[t + NT * k] - m);
        sum = warp_sum(sum);
        __syncthreads();
        if (!lane) red[warp] = sum;
        __syncthreads();
        if (warp == 0) {
            sum = (lane < 8) ? red[lane] : 0.f;
#pragma unroll
            for (int o = 4; o; o >>= 1) sum += __shfl_xor_sync(0xffffffffu, sum, o);
            if (!lane) bcs = sum;
        }
        __syncthreads();
        const float inv = 1.f / bcs;

        if (b == 0) {                             // attn_weights output
#pragma unroll
            for (int k = 0; k < 16; k++) {
                int s = t + NT * k;
                dout[V + H + s] = expf(g_scores[s] - m) * inv;
            }
        }

        const int sc = b >> 2;                    // rows [sc*64, sc*64+64)
        const int c = (b & 3) * NT + t;
        if (t < 64) w_sh[t] = expf(g_scores[sc * 64 + t] - m) * inv;
        __syncthreads();

        const float* base = enc + (long)(sc * 64) * H + c;
        float acc = 0.f;
#pragma unroll 8
        for (int s = 0; s < 64; s++)
            acc += w_sh[s] * base[(long)s * H];
        g_ctxpart[sc][c] = acc;
    }
    mid_sync();   // B3

    // ===== P4 (blocks 0..3): ctx reduce; kernel end publishes to k_logits
    if (b < 4) {
        int c = b * NT + t;
        float s = 0.f;
#pragma unroll
        for (int j = 0; j < 64; j++) s += g_ctxpart[j][c];
        g_ctx[c] = s;
    }
}

// ================= K3: logits (flat; measured 6.6 TB/s — FROZEN) ==============
__global__ void k_logits(const float* __restrict__ out_w,
                         const float* __restrict__ out_b,
                         float* __restrict__ dout) {
    __shared__ float4 cat[512];  // [h | ctx]
    int t = threadIdx.x;
    cat[t] = reinterpret_cast<const float4*>(g_h)[t];
    cat[256 + t] = reinterpret_cast<const float4*>(g_ctx)[t];
    __syncthreads();

    int warp = t >> 5, lane = t & 31;
    int r = blockIdx.x * 8 + warp;
    if (r >= V) return;
    const float4* wr = reinterpret_cast<const float4*>(out_w + (long)r * (2 * H));
    float acc = 0.f;
#pragma unroll
    for (int it = 0; it < 16; it++) {
        float4 w = wr[it * 32 + lane];
        float4 c = cat[it * 32 + lane];
        acc += w.x * c.x + w.y * c.y + w.z * c.z + w.w * c.w;
    }
    acc = warp_sum(acc);
    if (!lane) dout[r] = acc + out_b[r];
}

// ---------------- launch ----------------
extern "C" void kernel_launch(void* const* d_in, const int* in_sizes, int n_in,
                              void* d_out, int out_size) {
    const int* word = (const int*)d_in[0];
    const float* last_hidden = (const float*)d_in[1];
    const float* enc = (const float*)d_in[2];
    const float* emb = (const float*)d_in[3];
    const float* w_ih = (const float*)d_in[4];
    const float* w_hh = (const float*)d_in[5];
    const float* b_ih = (const float*)d_in[6];
    const float* b_hh = (const float*)d_in[7];
    const float* attn_w = (const float*)d_in[8];
    // d_in[9] = attn_b : constant pre-softmax shift -> softmax-invariant, dropped
    const float* out_w = (const float*)d_in[10];
    const float* out_b = (const float*)d_in[11];
    float* dout = (float*)d_out;

    k_gates<<<6 * H / 8, NT>>>(word, last_hidden, emb, w_ih, w_hh, b_ih, b_hh);
    k_mid<<<NMID, NT>>>(last_hidden, enc, attn_w, dout);
    k_logits<<<(V + 7) / 8, NT>>>(out_w, out_b, dout);
}

// round 14
// speedup vs baseline: 1.4605x; 1.0400x over previous
#include <cuda_runtime.h>
#include <math.h>

#define H 1024
#define V 50257
#define S 4096
#define NT 256
#define NMID 512        // persistent chain blocks, co-resident at 4/SM

// ---------------- scratch (__device__ globals) ----------------
__device__ float g_gi[3 * H];
__device__ float g_gh[3 * H];
__device__ float g_h[H];
__device__ float g_vpart[16][H];     // 16 j-chunks of 64 rows
__device__ float g_scores[S];
__device__ float g_ctx[H];           // accumulated via atomicAdd
__device__ unsigned g_cnt = 0;
__device__ unsigned g_gen = 0;

// ---------------- helpers ----------------
__device__ __forceinline__ float warp_sum(float v) {
#pragma unroll
    for (int o = 16; o; o >>= 1) v += __shfl_xor_sync(0xffffffffu, v, o);
    return v;
}

__device__ __forceinline__ void mid_sync() {
    __syncthreads();
    if (threadIdx.x == 0) {
        __threadfence();
        unsigned gen = *(volatile unsigned*)&g_gen;
        if (atomicAdd(&g_cnt, 1u) == NMID - 1) {
            g_cnt = 0;
            __threadfence();
            *(volatile unsigned*)&g_gen = gen + 1;
        } else {
            while (*(volatile unsigned*)&g_gen == gen) { }
        }
        __threadfence();
    }
    __syncthreads();
}

// ================= K1: chain (persistent 512 blocks, 3 barriers) ==============
__global__ void __launch_bounds__(NT, 4)
k_chain(const int* __restrict__ word,
        const float* __restrict__ last_hidden,
        const float* __restrict__ enc,
        const float* __restrict__ emb,
        const float* __restrict__ w_ih,
        const float* __restrict__ w_hh,
        const float* __restrict__ b_ih,
        const float* __restrict__ b_hh,
        const float* __restrict__ attn_w,
        float* __restrict__ dout) {
    __shared__ float4 sbuf4[512];   // [0..255]: x then h ; [256..511]: h_prev then v
    __shared__ float red[8];
    __shared__ float bcm, bcs;
    __shared__ float w_sh[32];
    float* h_sh = (float*)sbuf4;

    const int t = threadIdx.x;
    const int b = blockIdx.x;
    const int warp = t >> 5, lane = t & 31;
    const int gw = b * 8 + warp;                 // 4096 warps

    // ===== P1: gates — warp gw covers rows gw and gw+4096 (<6144)
    {
        const float* x = emb + (long)word[0] * H;
        sbuf4[t]       = reinterpret_cast<const float4*>(x)[t];
        sbuf4[256 + t] = reinterpret_cast<const float4*>(last_hidden)[t];
        __syncthreads();

        // block 511 zeroes g_ctx for this replay (ordered before P4 adds by barriers)
        if (b == NMID - 1 && t < 256) {
            reinterpret_cast<float4*>(g_ctx)[t] = make_float4(0.f, 0.f, 0.f, 0.f);
        }

#pragma unroll
        for (int k = 0; k < 2; k++) {
            int r = gw + k * 4096;
            if (r < 6 * H) {
                const float4* p;
                const float4* vec;
                float bias;
                float* outp;
                if (r < 3 * H) {
                    p = reinterpret_cast<const float4*>(w_ih + (long)r * H);
                    vec = sbuf4; bias = b_ih[r]; outp = &g_gi[r];
                } else {
                    int rr = r - 3 * H;
                    p = reinterpret_cast<const float4*>(w_hh + (long)rr * H);
                    vec = sbuf4 + 256; bias = b_hh[rr]; outp = &g_gh[rr];
                }
                float acc = 0.f;
#pragma unroll
                for (int it = 0; it < 8; it++) {
                    float4 w = p[it * 32 + lane];
                    float4 c = vec[it * 32 + lane];
                    acc += w.x * c.x + w.y * c.y + w.z * c.z + w.w * c.w;
                }
                acc = warp_sum(acc);
                if (!lane) *outp = acc + bias;
            }
        }
    }
    mid_sync();   // B1

    // ===== P2 (blocks 0..63): local GRU -> smem h ; v partials
    if (b < 64) {
#pragma unroll
        for (int k = 0; k < 4; k++) {
            int i = t + NT * k;
            float hp = ((const float*)(sbuf4 + 256))[i];   // h_prev still in shared
            float r = 1.f / (1.f + expf(-(g_gi[i] + g_gh[i])));
            float z = 1.f / (1.f + expf(-(g_gi[H + i] + g_gh[H + i])));
            float n = tanhf(g_gi[2 * H + i] + r * g_gh[2 * H + i]);
            float h = (1.f - z) * n + z * hp;
            h_sh[i] = h;                                    // overwrites x (done)
            if (b == 0) { g_h[i] = h; dout[V + i] = h; }    // hidden output + publish
        }
        __syncthreads();

        int jc = b >> 2;                          // 16 chunks of 64 rows
        int c = (b & 3) * NT + t;
        const float* base = attn_w + (long)(jc * 64) * H + c;
        float s = 0.f;
#pragma unroll 8
        for (int j = 0; j < 64; j++)
            s += base[(long)j * H] * h_sh[jc * 64 + j];
        g_vpart[jc][c] = s;
    }
    mid_sync();   // B2

    // ===== P3: local vred (all blocks) -> smem v ; scores ONE row per warp
    {
        float4 acc = make_float4(0.f, 0.f, 0.f, 0.f);
#pragma unroll
        for (int j = 0; j < 16; j++) {
            float4 pv = reinterpret_cast<const float4*>(g_vpart[j])[t];
            acc.x += pv.x; acc.y += pv.y; acc.z += pv.z; acc.w += pv.w;
        }
        sbuf4[256 + t] = acc;                     // v replaces h_prev
        __syncthreads();

        // gw in [0, 4096) == S exactly; attn_b softmax-invariant, dropped
        const float4* er = reinterpret_cast<const float4*>(enc + (long)gw * H);
        float a = 0.f;
#pragma unroll
        for (int it = 0; it < 8; it++) {
            float4 e = er[it * 32 + lane];
            float4 vv = sbuf4[256 + it * 32 + lane];
            a += e.x * vv.x + e.y * vv.y + e.z * vv.z + e.w * vv.w;
        }
        a = warp_sum(a);
        if (!lane) g_scores[gw] = a;
    }
    mid_sync();   // B3

    // ===== P4: local two-pass softmax stats ; ctx partials via atomicAdd
    {
        float m = -INFINITY;
#pragma unroll
        for (int k = 0; k < 16; k++) m = fmaxf(m, g_scores[t + NT * k]);
#pragma unroll
        for (int o = 16; o; o >>= 1) m = fmaxf(m, __shfl_xor_sync(0xffffffffu, m, o));
        if (!lane) red[warp] = m;
        __syncthreads();
        if (warp == 0) {
            m = (lane < 8) ? red[lane] : -INFINITY;
#pragma unroll
            for (int o = 4; o; o >>= 1) m = fmaxf(m, __shfl_xor_sync(0xffffffffu, m, o));
            if (!lane) bcm = m;
        }
        __syncthreads();
        m = bcm;
        float sum = 0.f;
#pragma unroll
        for (int k = 0; k < 16; k++) sum += expf(g_scores[t + NT * k] - m);
        sum = warp_sum(sum);
        __syncthreads();
        if (!lane) red[warp] = sum;
        __syncthreads();
        if (warp == 0) {
            sum = (lane < 8) ? red[lane] : 0.f;
#pragma unroll
            for (int o = 4; o; o >>= 1) sum += __shfl_xor_sync(0xffffffffu, sum, o);
            if (!lane) bcs = sum;
        }
        __syncthreads();
        const float inv = 1.f / bcs;

        if (b == 0) {                             // attn_weights output
#pragma unroll
            for (int k = 0; k < 16; k++) {
                int s = t + NT * k;
                dout[V + H + s] = expf(g_scores[s] - m) * inv;
            }
        }

        // ctx partial: block b covers rows [sc*32, sc*32+32), cols (b&3)*256+t
        const int sc = b >> 2;                    // 128 chunks of 32 rows
        const int c = (b & 3) * NT + t;
        if (t < 32) w_sh[t] = expf(g_scores[sc * 32 + t] - m) * inv;
        __syncthreads();

        const float* base = enc + (long)(sc * 32) * H + c;   // L2-hot after scores
        float acc = 0.f;
#pragma unroll 8
        for (int s = 0; s < 32; s++)
            acc += w_sh[s] * base[(long)s * H];
        atomicAdd(&g_ctx[c], acc);
    }
    // kernel end publishes g_h / g_ctx to k_logits
}

// ================= K2: logits (flat; measured 6.6 TB/s — FROZEN) ==============
__global__ void k_logits(const float* __restrict__ out_w,
                         const float* __restrict__ out_b,
                         float* __restrict__ dout) {
    __shared__ float4 cat[512];  // [h | ctx]
    int t = threadIdx.x;
    cat[t] = reinterpret_cast<const float4*>(g_h)[t];
    cat[256 + t] = reinterpret_cast<const float4*>(g_ctx)[t];
    __syncthreads();

    int warp = t >> 5, lane = t & 31;
    int r = blockIdx.x * 8 + warp;
    if (r >= V) return;
    const float4* wr = reinterpret_cast<const float4*>(out_w + (long)r * (2 * H));
    float acc = 0.f;
#pragma unroll
    for (int it = 0; it < 16; it++) {
        float4 w = wr[it * 32 + lane];
        float4 c = cat[it * 32 + lane];
        acc += w.x * c.x + w.y * c.y + w.z * c.z + w.w * c.w;
    }
    acc = warp_sum(acc);
    if (!lane) dout[r] = acc + out_b[r];
}

// ---------------- launch ----------------
extern "C" void kernel_launch(void* const* d_in, const int* in_sizes, int n_in,
                              void* d_out, int out_size) {
    const int* word = (const int*)d_in[0];
    const float* last_hidden = (const float*)d_in[1];
    const float* enc = (const float*)d_in[2];
    const float* emb = (const float*)d_in[3];
    const float* w_ih = (const float*)d_in[4];
    const float* w_hh = (const float*)d_in[5];
    const float* b_ih = (const float*)d_in[6];
    const float* b_hh = (const float*)d_in[7];
    const float* attn_w = (const float*)d_in[8];
    // d_in[9] = attn_b : constant pre-softmax shift -> softmax-invariant, dropped
    const float* out_w = (const float*)d_in[10];
    const float* out_b = (const float*)d_in[11];
    float* dout = (float*)d_out;

    k_chain<<<NMID, NT>>>(word, last_hidden, enc, emb, w_ih, w_hh, b_ih, b_hh,
                          attn_w, dout);
    k_logits<<<(V + 7) / 8, NT>>>(out_w, out_b, dout);
}

// round 15
// speedup vs baseline: 1.6266x; 1.1137x over previous
#include <cuda_runtime.h>
#include <math.h>

#define H 1024
#define V 50257
#define S 4096
#define NT 256
#define NCHAIN 256      // co-resident (2/SM); barriers count these

// ---------------- scratch (__device__ globals) ----------------
__device__ float g_gi[3 * H];
__device__ float g_gh[3 * H];
__device__ float g_h[H];
__device__ float g_vpart[16][H];     // 16 j-chunks of 64 rows
__device__ float g_scores[S];
__device__ float g_ctx[H];           // accumulated via atomicAdd in P4
__device__ unsigned g_cnt = 0;
__device__ unsigned g_gen = 0;

// ---------------- helpers ----------------
__device__ __forceinline__ float warp_sum(float v) {
#pragma unroll
    for (int o = 16; o; o >>= 1) v += __shfl_xor_sync(0xffffffffu, v, o);
    return v;
}

__device__ __forceinline__ void chain_sync() {
    __syncthreads();
    if (threadIdx.x == 0) {
        __threadfence();
        unsigned gen = *(volatile unsigned*)&g_gen;
        if (atomicAdd(&g_cnt, 1u) == NCHAIN - 1) {
            g_cnt = 0;
            __threadfence();
            *(volatile unsigned*)&g_gen = gen + 1;
        } else {
            while (*(volatile unsigned*)&g_gen == gen) { }
        }
        __threadfence();
    }
    __syncthreads();
}

// ================= K1: chain (persistent 256 blocks, 3 barriers) ==============
__global__ void __launch_bounds__(NT, 2)
k_chain(const int* __restrict__ word,
        const float* __restrict__ last_hidden,
        const float* __restrict__ enc,
        const float* __restrict__ emb,
        const float* __restrict__ w_ih,
        const float* __restrict__ w_hh,
        const float* __restrict__ b_ih,
        const float* __restrict__ b_hh,
        const float* __restrict__ attn_w,
        float* __restrict__ dout) {
    __shared__ float4 sbuf4[512];   // [0..255]: x then h ; [256..511]: h_prev then v
    __shared__ float red[8];
    __shared__ float bcm, bcs;
    __shared__ float w_sh[64];
    float* h_sh = (float*)sbuf4;

    const int t = threadIdx.x;
    const int b = blockIdx.x;
    const int warp = t >> 5, lane = t & 31;
    const int nwarp = NCHAIN * (NT / 32);        // 2048
    const int gw = b * (NT / 32) + warp;

    // ===== P1: gates — 3 rows per warp, loads interleaved (MLP=3)
    {
        const float* x = emb + (long)word[0] * H;
        sbuf4[t]       = reinterpret_cast<const float4*>(x)[t];
        sbuf4[256 + t] = reinterpret_cast<const float4*>(last_hidden)[t];
        __syncthreads();

        // idle-ish last block zeroes g_ctx for this replay (ordered before P4
        // atomics by barriers 1..3)
        if (b == NCHAIN - 1) {
            reinterpret_cast<float4*>(g_ctx)[t] = make_float4(0.f, 0.f, 0.f, 0.f);
        }

        const float4* p[3];
        const float4* vv[3];
        float bias[3];
        float* outp[3];
#pragma unroll
        for (int k = 0; k < 3; k++) {
            int r = gw + k * nwarp;              // 6144 = 3 * 2048 exact
            if (r < 3 * H) {
                p[k] = reinterpret_cast<const float4*>(w_ih + (long)r * H);
                vv[k] = sbuf4; bias[k] = b_ih[r]; outp[k] = &g_gi[r];
            } else {
                int rr = r - 3 * H;
                p[k] = reinterpret_cast<const float4*>(w_hh + (long)rr * H);
                vv[k] = sbuf4 + 256; bias[k] = b_hh[rr]; outp[k] = &g_gh[rr];
            }
        }
        float a0 = 0.f, a1 = 0.f, a2 = 0.f;
#pragma unroll
        for (int it = 0; it < 8; it++) {
            float4 w0 = p[0][it * 32 + lane];
            float4 w1 = p[1][it * 32 + lane];
            float4 w2 = p[2][it * 32 + lane];
            float4 c0 = vv[0][it * 32 + lane];
            float4 c1 = vv[1][it * 32 + lane];
            float4 c2 = vv[2][it * 32 + lane];
            a0 += w0.x * c0.x + w0.y * c0.y + w0.z * c0.z + w0.w * c0.w;
            a1 += w1.x * c1.x + w1.y * c1.y + w1.z * c1.z + w1.w * c1.w;
            a2 += w2.x * c2.x + w2.y * c2.y + w2.z * c2.z + w2.w * c2.w;
        }
        a0 = warp_sum(a0); a1 = warp_sum(a1); a2 = warp_sum(a2);
        if (!lane) { *outp[0] = a0 + bias[0]; *outp[1] = a1 + bias[1]; *outp[2] = a2 + bias[2]; }
    }
    chain_sync();   // B1

    // ===== P2 (blocks 0..63): local GRU -> smem h ; v partials
    if (b < 64) {
#pragma unroll
        for (int k = 0; k < 4; k++) {
            int i = t + NT * k;
            float hp = ((const float*)(sbuf4 + 256))[i];   // h_prev still in shared
            float r = 1.f / (1.f + expf(-(g_gi[i] + g_gh[i])));
            float z = 1.f / (1.f + expf(-(g_gi[H + i] + g_gh[H + i])));
            float n = tanhf(g_gi[2 * H + i] + r * g_gh[2 * H + i]);
            float h = (1.f - z) * n + z * hp;
            h_sh[i] = h;                                    // overwrites x (done)
            if (b == 0) { g_h[i] = h; dout[V + i] = h; }    // hidden output + publish
        }
        __syncthreads();

        int jc = b >> 2;                          // 16 chunks of 64 rows
        int c = (b & 3) * NT + t;
        const float* base = attn_w + (long)(jc * 64) * H + c;
        float s = 0.f;
#pragma unroll 8
        for (int j = 0; j < 64; j++)
            s += base[(long)j * H] * h_sh[jc * 64 + j];
        g_vpart[jc][c] = s;
    }
    chain_sync();   // B2

    // ===== P3: local vred (all blocks) -> smem v ; scores 2 rows/warp interleaved
    {
        float4 acc = make_float4(0.f, 0.f, 0.f, 0.f);
#pragma unroll
        for (int j = 0; j < 16; j++) {
            float4 pv = reinterpret_cast<const float4*>(g_vpart[j])[t];
            acc.x += pv.x; acc.y += pv.y; acc.z += pv.z; acc.w += pv.w;
        }
        sbuf4[256 + t] = acc;                     // v replaces h_prev
        __syncthreads();

        const float4* e0 = reinterpret_cast<const float4*>(enc + (long)gw * H);
        const float4* e1 = reinterpret_cast<const float4*>(enc + (long)(gw + nwarp) * H);
        float a0 = 0.f, a1 = 0.f;
#pragma unroll
        for (int it = 0; it < 8; it++) {
            float4 x0 = e0[it * 32 + lane];
            float4 x1 = e1[it * 32 + lane];
            float4 vv = sbuf4[256 + it * 32 + lane];
            a0 += x0.x * vv.x + x0.y * vv.y + x0.z * vv.z + x0.w * vv.w;
            a1 += x1.x * vv.x + x1.y * vv.y + x1.z * vv.z + x1.w * vv.w;
        }
        a0 = warp_sum(a0); a1 = warp_sum(a1);
        if (!lane) { g_scores[gw] = a0; g_scores[gw + nwarp] = a1; }
        // attn_b is a constant pre-softmax shift -> softmax-invariant, dropped
    }
    chain_sync();   // B3

    // ===== P4: local softmax stats ; ctx partials -> atomicAdd(g_ctx)
    {
        float e_loc[16];
        float x[16];
        float m = -INFINITY;
#pragma unroll
        for (int k = 0; k < 16; k++) {
            x[k] = g_scores[t + NT * k];
            m = fmaxf(m, x[k]);
        }
#pragma unroll
        for (int o = 16; o; o >>= 1) m = fmaxf(m, __shfl_xor_sync(0xffffffffu, m, o));
        if (!lane) red[warp] = m;
        __syncthreads();
        if (warp == 0) {
            m = (lane < 8) ? red[lane] : -INFINITY;
#pragma unroll
            for (int o = 4; o; o >>= 1) m = fmaxf(m, __shfl_xor_sync(0xffffffffu, m, o));
            if (!lane) bcm = m;
        }
        __syncthreads();
        m = bcm;
        float sum = 0.f;
#pragma unroll
        for (int k = 0; k < 16; k++) { e_loc[k] = expf(x[k] - m); sum += e_loc[k]; }
        sum = warp_sum(sum);
        __syncthreads();
        if (!lane) red[warp] = sum;
        __syncthreads();
        if (warp == 0) {
            sum = (lane < 8) ? red[lane] : 0.f;
#pragma unroll
            for (int o = 4; o; o >>= 1) sum += __shfl_xor_sync(0xffffffffu, sum, o);
            if (!lane) bcs = sum;
        }
        __syncthreads();
        const float inv = 1.f / bcs;

        if (b == 0) {                             // attn_weights output
#pragma unroll
            for (int k = 0; k < 16; k++)
                dout[V + H + t + NT * k] = e_loc[k] * inv;
        }

        // ctx partial: block b -> rows [sc*64, sc*64+64), cols (b&3)*256+t
        const int sc = b >> 2;                    // 64 chunks of 64 rows
        const int c = (b & 3) * NT + t;
#pragma unroll
        for (int k = 0; k < 16; k++) {
            int s = t + NT * k;
            int j = s - sc * 64;
            if (j >= 0 && j < 64) w_sh[j] = e_loc[k] * inv;
        }
        __syncthreads();

        const float* base = enc + (long)(sc * 64) * H + c;   // L2-hot after scores
        float acc = 0.f;
#pragma unroll 8
        for (int s = 0; s < 64; s++)
            acc += w_sh[s] * base[(long)s * H];
        atomicAdd(&g_ctx[c], acc);                // 64 adds/address, spread
    }
    // kernel end publishes g_h / g_ctx to k_logits
}

// ================= K2: logits (flat; measured 6.6 TB/s — FROZEN) ==============
__global__ void k_logits(const float* __restrict__ out_w,
                         const float* __restrict__ out_b,
                         float* __restrict__ dout) {
    __shared__ float4 cat[512];  // [h | ctx]
    int t = threadIdx.x;
    cat[t] = reinterpret_cast<const float4*>(g_h)[t];
    cat[256 + t] = reinterpret_cast<const float4*>(g_ctx)[t];
    __syncthreads();

    int warp = t >> 5, lane = t & 31;
    int r = blockIdx.x * 8 + warp;
    if (r >= V) return;
    const float4* wr = reinterpret_cast<const float4*>(out_w + (long)r * (2 * H));
    float acc = 0.f;
#pragma unroll
    for (int it = 0; it < 16; it++) {
        float4 w = wr[it * 32 + lane];
        float4 c = cat[it * 32 + lane];
        acc += w.x * c.x + w.y * c.y + w.z * c.z + w.w * c.w;
    }
    acc = warp_sum(acc);
    if (!lane) dout[r] = acc + out_b[r];
}

// ---------------- launch ----------------
extern "C" void kernel_launch(void* const* d_in, const int* in_sizes, int n_in,
                              void* d_out, int out_size) {
    const int* word = (const int*)d_in[0];
    const float* last_hidden = (const float*)d_in[1];
    const float* enc = (const float*)d_in[2];
    const float* emb = (const float*)d_in[3];
    const float* w_ih = (const float*)d_in[4];
    const float* w_hh = (const float*)d_in[5];
    const float* b_ih = (const float*)d_in[6];
    const float* b_hh = (const float*)d_in[7];
    const float* attn_w = (const float*)d_in[8];
    // d_in[9] = attn_b : constant pre-softmax shift -> softmax-invariant, dropped
    const float* out_w = (const float*)d_in[10];
    const float* out_b = (const float*)d_in[11];
    float* dout = (float*)d_out;

    k_chain<<<NCHAIN, NT>>>(word, last_hidden, enc, emb, w_ih, w_hh, b_ih, b_hh,
                            attn_w, dout);
    k_logits<<<(V + 7) / 8, NT>>>(out_w, out_b, dout);
}